// round 5
// baseline (speedup 1.0000x reference)
#include <cuda_runtime.h>
#include <stdint.h>

#define NN 100000
#define D 128

// Scratch (device globals -- no runtime allocation allowed)
__device__ __align__(16) float g_inv[NN];
__device__ __align__(16) float g_msum[(size_t)NN * D];
__device__ __align__(16) float g_h1[(size_t)NN * D];
__device__ __align__(16) float g_h2[(size_t)NN * D];
__device__ int g_is64;

// ---------------------------------------------------------------------------
// Packed f32x2 helpers (Blackwell FFMA2 -- only reachable via PTX)
// ---------------------------------------------------------------------------
__device__ __forceinline__ void ffma2(unsigned long long& acc,
                                      unsigned long long a,
                                      unsigned long long b) {
    asm("fma.rn.f32x2 %0, %1, %2, %0;" : "+l"(acc) : "l"(a), "l"(b));
}
__device__ __forceinline__ unsigned long long pack2(float lo, float hi) {
    unsigned long long r;
    asm("mov.b64 %0, {%1, %2};" : "=l"(r) : "f"(lo), "f"(hi));
    return r;
}
__device__ __forceinline__ float2 unpack2(unsigned long long v) {
    float lo, hi;
    asm("mov.b64 {%0, %1}, %2;" : "=f"(lo), "=f"(hi) : "l"(v));
    return make_float2(lo, hi);
}

// ---------------------------------------------------------------------------
// Edge-index dtype detection (reference says int64; default JAX yields int32)
// ---------------------------------------------------------------------------
__global__ void detect_kernel(const unsigned int* __restrict__ ei32,
                              int npairs) {
    __shared__ int any;
    if (threadIdx.x == 0) any = 0;
    __syncthreads();
    int found = 0;
    for (int i = threadIdx.x; i < npairs; i += blockDim.x)
        if (ei32[2 * i + 1] != 0u) found = 1;
    if (found) any = 1;   // benign race
    __syncthreads();
    if (threadIdx.x == 0) g_is64 = (any == 0);
}

__device__ __forceinline__ int edge_at(const void* __restrict__ ei, int i) {
    if (g_is64) return (int)((const long long*)ei)[i];
    return ((const int*)ei)[i];
}

// ---------------------------------------------------------------------------
// Zeroing
// ---------------------------------------------------------------------------
__global__ void zero_inv_kernel(int n) {
    int i = blockIdx.x * blockDim.x + threadIdx.x;
    if (i < n) g_inv[i] = 0.0f;
}

__global__ void zero_msum_kernel(int n4) {  // n4 = N*D/4
    int i = blockIdx.x * blockDim.x + threadIdx.x;
    if (i < n4) ((float4*)g_msum)[i] = make_float4(0.f, 0.f, 0.f, 0.f);
}

// ---------------------------------------------------------------------------
// Degree and inverse degree
// ---------------------------------------------------------------------------
__global__ void deg_kernel(const void* __restrict__ ei, int E, int n) {
    int e = blockIdx.x * blockDim.x + threadIdx.x;
    if (e >= E) return;
    unsigned d = min((unsigned)edge_at(ei, E + e), (unsigned)(n - 1));
    atomicAdd(&g_inv[d], 1.0f);
}

__global__ void inv_kernel(int n) {
    int i = blockIdx.x * blockDim.x + threadIdx.x;
    if (i < n) g_inv[i] = 1.0f / fmaxf(g_inv[i], 1.0f);
}

// ---------------------------------------------------------------------------
// Edge scatter: msum[dst] += h[src]
// One warp per edge; each lane owns 4 consecutive floats (16B). A single
// red.global.add.v4.f32 per lane -> 1 L2 reduction op per 16B instead of 4.
// Warp covers the full 512B row contiguously.
// ---------------------------------------------------------------------------
template <int SRC>
__global__ void __launch_bounds__(256) scatter_kernel(
    const float* __restrict__ x, const void* __restrict__ ei, int E, int n) {
    int tid = blockIdx.x * blockDim.x + threadIdx.x;
    int e = tid >> 5;
    if (e >= E) return;
    int lane = tid & 31;
    unsigned s = min((unsigned)edge_at(ei, e), (unsigned)(n - 1));
    unsigned d = min((unsigned)edge_at(ei, E + e), (unsigned)(n - 1));
    const float* h = (SRC == 0) ? x : g_h1;
    const float4 v = *(const float4*)(h + (size_t)s * D + lane * 4);
    float* p = g_msum + (size_t)d * D + lane * 4;
    asm volatile(
        "{ .reg .u64 pg; cvta.to.global.u64 pg, %0;\n\t"
        "  red.global.add.v4.f32 [pg], {%1,%2,%3,%4}; }"
        :: "l"(p), "f"(v.x), "f"(v.y), "f"(v.z), "f"(v.w)
        : "memory");
}

// ---------------------------------------------------------------------------
// Fused SAGE layer: out = relu( (msum*inv) @ Wl + bl + h @ Wr )
// 256 threads, 2 nodes/thread, 32 out cols/block (grid.y=4).
// Inner product uses packed FFMA2: accumulators are f32x2 pairs.
// ---------------------------------------------------------------------------
template <int SRC, int OUT>
__global__ void __launch_bounds__(256) sage_kernel(
    const float* __restrict__ x, const float* __restrict__ Wl,
    const float* __restrict__ bl, const float* __restrict__ Wr, int n) {
    __shared__ float sWl[D * 32];
    __shared__ float sWr[D * 32];
    __shared__ float sb[32];

    const int j0 = blockIdx.y * 32;
    for (int idx = threadIdx.x; idx < D * 32; idx += 256) {
        int k = idx >> 5, jj = idx & 31;
        sWl[idx] = Wl[k * D + j0 + jj];
        sWr[idx] = Wr[k * D + j0 + jj];
    }
    if (threadIdx.x < 32) sb[threadIdx.x] = bl[j0 + threadIdx.x];
    __syncthreads();

    const float* h = (SRC == 0) ? x : g_h1;
    float* out = (OUT == 1) ? g_h1 : g_h2;

    const int n0 = blockIdx.x * 512 + threadIdx.x;
    const int n1 = n0 + 256;
    const int c0 = min(n0, n - 1), c1 = min(n1, n - 1);
    const float inv0 = g_inv[c0], inv1 = g_inv[c1];
    const float4* m0p = (const float4*)(g_msum + (size_t)c0 * D);
    const float4* m1p = (const float4*)(g_msum + (size_t)c1 * D);
    const float4* h0p = (const float4*)(h + (size_t)c0 * D);
    const float4* h1p = (const float4*)(h + (size_t)c1 * D);

    // 16 packed accumulators per node: pair p covers cols (2p, 2p+1)
    unsigned long long acc0[16], acc1[16];
#pragma unroll
    for (int p = 0; p < 16; p++) {
        unsigned long long b = pack2(sb[2 * p], sb[2 * p + 1]);
        acc0[p] = b;
        acc1[p] = b;
    }

#pragma unroll 2
    for (int k4 = 0; k4 < 32; ++k4) {
        float4 m0 = m0p[k4], q0 = h0p[k4];
        float4 m1 = m1p[k4], q1 = h1p[k4];
        float a0s[4] = {m0.x * inv0, m0.y * inv0, m0.z * inv0, m0.w * inv0};
        float a1s[4] = {m1.x * inv1, m1.y * inv1, m1.z * inv1, m1.w * inv1};
        float r0s[4] = {q0.x, q0.y, q0.z, q0.w};
        float r1s[4] = {q1.x, q1.y, q1.z, q1.w};
#pragma unroll
        for (int kk = 0; kk < 4; ++kk) {
            const int kbase = (k4 * 4 + kk) * 32;
            unsigned long long pa0 = pack2(a0s[kk], a0s[kk]);
            unsigned long long pr0 = pack2(r0s[kk], r0s[kk]);
            unsigned long long pa1 = pack2(a1s[kk], a1s[kk]);
            unsigned long long pr1 = pack2(r1s[kk], r1s[kk]);
#pragma unroll
            for (int jj = 0; jj < 8; ++jj) {
                ulonglong2 wl = *(const ulonglong2*)&sWl[kbase + jj * 4];
                ulonglong2 wr = *(const ulonglong2*)&sWr[kbase + jj * 4];
                ffma2(acc0[jj * 2 + 0], pa0, wl.x);
                ffma2(acc0[jj * 2 + 0], pr0, wr.x);
                ffma2(acc0[jj * 2 + 1], pa0, wl.y);
                ffma2(acc0[jj * 2 + 1], pr0, wr.y);
                ffma2(acc1[jj * 2 + 0], pa1, wl.x);
                ffma2(acc1[jj * 2 + 0], pr1, wr.x);
                ffma2(acc1[jj * 2 + 1], pa1, wl.y);
                ffma2(acc1[jj * 2 + 1], pr1, wr.y);
            }
        }
    }

    if (n0 < n) {
        float4* o = (float4*)(out + (size_t)n0 * D + j0);
#pragma unroll
        for (int jj = 0; jj < 8; ++jj) {
            float2 a = unpack2(acc0[jj * 2 + 0]);
            float2 b = unpack2(acc0[jj * 2 + 1]);
            o[jj] = make_float4(fmaxf(a.x, 0.f), fmaxf(a.y, 0.f),
                                fmaxf(b.x, 0.f), fmaxf(b.y, 0.f));
        }
    }
    if (n1 < n) {
        float4* o = (float4*)(out + (size_t)n1 * D + j0);
#pragma unroll
        for (int jj = 0; jj < 8; ++jj) {
            float2 a = unpack2(acc1[jj * 2 + 0]);
            float2 b = unpack2(acc1[jj * 2 + 1]);
            o[jj] = make_float4(fmaxf(a.x, 0.f), fmaxf(a.y, 0.f),
                                fmaxf(b.x, 0.f), fmaxf(b.y, 0.f));
        }
    }
}

// ---------------------------------------------------------------------------
// Fused MLP head: out = relu( relu(g_h2 @ W0 + b0) @ W1 + b1 )
// Packed FFMA2 accumulators for the 128x64 GEMM.
// ---------------------------------------------------------------------------
__global__ void __launch_bounds__(256) lin_kernel(
    const float* __restrict__ W0, const float* __restrict__ b0,
    const float* __restrict__ W1, const float* __restrict__ b1,
    float* __restrict__ out, int n) {
    __shared__ float sW0[D * 64];
    __shared__ float sW1[64 * 8];
    __shared__ float sb0[64];
    __shared__ float sb1[8];

    for (int idx = threadIdx.x; idx < D * 64; idx += 256) sW0[idx] = W0[idx];
    for (int idx = threadIdx.x; idx < 64 * 8; idx += 256) sW1[idx] = W1[idx];
    if (threadIdx.x < 64) sb0[threadIdx.x] = b0[threadIdx.x];
    if (threadIdx.x < 8) sb1[threadIdx.x] = b1[threadIdx.x];
    __syncthreads();

    const int n0 = blockIdx.x * 256 + threadIdx.x;
    const int c0 = min(n0, n - 1);
    const float4* hp = (const float4*)(g_h2 + (size_t)c0 * D);

    unsigned long long acc[32];
#pragma unroll
    for (int p = 0; p < 32; p++) acc[p] = pack2(sb0[2 * p], sb0[2 * p + 1]);

#pragma unroll 2
    for (int k4 = 0; k4 < 32; ++k4) {
        float4 hv = hp[k4];
        float r[4] = {hv.x, hv.y, hv.z, hv.w};
#pragma unroll
        for (int kk = 0; kk < 4; ++kk) {
            const int kbase = (k4 * 4 + kk) * 64;
            unsigned long long pr = pack2(r[kk], r[kk]);
#pragma unroll
            for (int jj = 0; jj < 16; ++jj) {
                ulonglong2 w = *(const ulonglong2*)&sW0[kbase + jj * 4];
                ffma2(acc[jj * 2 + 0], pr, w.x);
                ffma2(acc[jj * 2 + 1], pr, w.y);
            }
        }
    }

    float o[8];
#pragma unroll
    for (int j = 0; j < 8; j++) o[j] = sb1[j];
    const float4* W14 = (const float4*)sW1;
#pragma unroll
    for (int p = 0; p < 32; ++p) {
        float2 t2 = unpack2(acc[p]);
        float t0 = fmaxf(t2.x, 0.f);
        float t1 = fmaxf(t2.y, 0.f);
        {
            float4 wa = W14[(2 * p) * 2 + 0];
            float4 wb = W14[(2 * p) * 2 + 1];
            o[0] = fmaf(t0, wa.x, o[0]);
            o[1] = fmaf(t0, wa.y, o[1]);
            o[2] = fmaf(t0, wa.z, o[2]);
            o[3] = fmaf(t0, wa.w, o[3]);
            o[4] = fmaf(t0, wb.x, o[4]);
            o[5] = fmaf(t0, wb.y, o[5]);
            o[6] = fmaf(t0, wb.z, o[6]);
            o[7] = fmaf(t0, wb.w, o[7]);
        }
        {
            float4 wa = W14[(2 * p + 1) * 2 + 0];
            float4 wb = W14[(2 * p + 1) * 2 + 1];
            o[0] = fmaf(t1, wa.x, o[0]);
            o[1] = fmaf(t1, wa.y, o[1]);
            o[2] = fmaf(t1, wa.z, o[2]);
            o[3] = fmaf(t1, wa.w, o[3]);
            o[4] = fmaf(t1, wb.x, o[4]);
            o[5] = fmaf(t1, wb.y, o[5]);
            o[6] = fmaf(t1, wb.z, o[6]);
            o[7] = fmaf(t1, wb.w, o[7]);
        }
    }

    if (n0 < n) {
        float4* op = (float4*)(out + (size_t)n0 * 8);
        op[0] = make_float4(fmaxf(o[0], 0.f), fmaxf(o[1], 0.f),
                            fmaxf(o[2], 0.f), fmaxf(o[3], 0.f));
        op[1] = make_float4(fmaxf(o[4], 0.f), fmaxf(o[5], 0.f),
                            fmaxf(o[6], 0.f), fmaxf(o[7], 0.f));
    }
}

// ---------------------------------------------------------------------------
// Launcher (no allocation, graph-capturable)
// ---------------------------------------------------------------------------
extern "C" void kernel_launch(void* const* d_in, const int* in_sizes, int n_in,
                              void* d_out, int out_size) {
    const float* x    = (const float*)d_in[0];
    const void*  ei   = d_in[1];
    const float* s0Wl = (const float*)d_in[2];
    const float* s0bl = (const float*)d_in[3];
    const float* s0Wr = (const float*)d_in[4];
    const float* s1Wl = (const float*)d_in[5];
    const float* s1bl = (const float*)d_in[6];
    const float* s1Wr = (const float*)d_in[7];
    const float* l0W  = (const float*)d_in[8];
    const float* l0b  = (const float*)d_in[9];
    const float* l1W  = (const float*)d_in[10];
    const float* l1b  = (const float*)d_in[11];
    float* out = (float*)d_out;

    const int N = in_sizes[0] / D;
    const int E = in_sizes[1] / 2;
    const int ND4 = N * D / 4;

    detect_kernel<<<1, 256>>>((const unsigned int*)ei, 2048);

    zero_inv_kernel<<<(N + 255) / 256, 256>>>(N);
    deg_kernel<<<(E + 255) / 256, 256>>>(ei, E, N);
    inv_kernel<<<(N + 255) / 256, 256>>>(N);

    const long long total = (long long)E * 32;
    const int sc_blocks = (int)((total + 255) / 256);
    dim3 sgrid((N + 511) / 512, 4);

    // layer 0
    zero_msum_kernel<<<(ND4 + 255) / 256, 256>>>(ND4);
    scatter_kernel<0><<<sc_blocks, 256>>>(x, ei, E, N);
    sage_kernel<0, 1><<<sgrid, 256>>>(x, s0Wl, s0bl, s0Wr, N);

    // layer 1
    zero_msum_kernel<<<(ND4 + 255) / 256, 256>>>(ND4);
    scatter_kernel<1><<<sc_blocks, 256>>>(x, ei, E, N);
    sage_kernel<1, 2><<<sgrid, 256>>>(x, s1Wl, s1bl, s1Wr, N);

    // MLP head
    lin_kernel<<<(N + 255) / 256, 256>>>(l0W, l0b, l1W, l1b, out, N);
}

// round 6
// speedup vs baseline: 1.1233x; 1.1233x over previous
#include <cuda_runtime.h>
#include <stdint.h>

#define NN 100000
#define NE 600000
#define D 128
#define SCAN_B 1024

// Scratch (device globals -- no runtime allocation allowed)
__device__ __align__(16) float g_msum[(size_t)NN * D];
__device__ __align__(16) float g_h1[(size_t)NN * D];
__device__ __align__(16) float g_h2[(size_t)NN * D];
__device__ int g_cnt[NN];
__device__ int g_fill[NN];
__device__ int g_rowptr[NN + 1];
__device__ int g_col[NE];
__device__ int g_blocksum[128];
__device__ int g_blockoff[128];
__device__ int g_is64;

// ---------------------------------------------------------------------------
// Packed f32x2 helpers (Blackwell FFMA2 -- only reachable via PTX)
// ---------------------------------------------------------------------------
__device__ __forceinline__ void ffma2(unsigned long long& acc,
                                      unsigned long long a,
                                      unsigned long long b) {
    asm("fma.rn.f32x2 %0, %1, %2, %0;" : "+l"(acc) : "l"(a), "l"(b));
}
__device__ __forceinline__ unsigned long long pack2(float lo, float hi) {
    unsigned long long r;
    asm("mov.b64 %0, {%1, %2};" : "=l"(r) : "f"(lo), "f"(hi));
    return r;
}
__device__ __forceinline__ float2 unpack2(unsigned long long v) {
    float lo, hi;
    asm("mov.b64 {%0, %1}, %2;" : "=f"(lo), "=f"(hi) : "l"(v));
    return make_float2(lo, hi);
}

// ---------------------------------------------------------------------------
// Edge-index dtype detection (reference says int64; default JAX yields int32)
// ---------------------------------------------------------------------------
__global__ void detect_kernel(const unsigned int* __restrict__ ei32,
                              int npairs) {
    __shared__ int any;
    if (threadIdx.x == 0) any = 0;
    __syncthreads();
    int found = 0;
    for (int i = threadIdx.x; i < npairs; i += blockDim.x)
        if (ei32[2 * i + 1] != 0u) found = 1;
    if (found) any = 1;   // benign race
    __syncthreads();
    if (threadIdx.x == 0) g_is64 = (any == 0);
}

__device__ __forceinline__ int edge_at(const void* __restrict__ ei, int i) {
    if (g_is64) return (int)((const long long*)ei)[i];
    return ((const int*)ei)[i];
}

// ---------------------------------------------------------------------------
// CSR build: histogram -> block scan -> fill
// ---------------------------------------------------------------------------
__global__ void zero_cnt_kernel(int n) {
    int i = blockIdx.x * blockDim.x + threadIdx.x;
    if (i < n) { g_cnt[i] = 0; g_fill[i] = 0; }
}

__global__ void hist_kernel(const void* __restrict__ ei, int E, int n) {
    int e = blockIdx.x * blockDim.x + threadIdx.x;
    if (e >= E) return;
    unsigned d = min((unsigned)edge_at(ei, E + e), (unsigned)(n - 1));
    atomicAdd(&g_cnt[d], 1);
}

__global__ void __launch_bounds__(SCAN_B) scan1_kernel(int n) {
    __shared__ int sm[SCAN_B];
    int i = blockIdx.x * SCAN_B + threadIdx.x;
    sm[threadIdx.x] = (i < n) ? g_cnt[i] : 0;
    __syncthreads();
    for (int off = SCAN_B / 2; off > 0; off >>= 1) {
        if (threadIdx.x < off) sm[threadIdx.x] += sm[threadIdx.x + off];
        __syncthreads();
    }
    if (threadIdx.x == 0) g_blocksum[blockIdx.x] = sm[0];
}

__global__ void scan2_kernel(int nb, int n, int E) {
    if (threadIdx.x == 0) {
        int run = 0;
        for (int b = 0; b < nb; b++) { g_blockoff[b] = run; run += g_blocksum[b]; }
        g_rowptr[n] = E;
    }
}

__global__ void __launch_bounds__(SCAN_B) scan3_kernel(int n) {
    __shared__ int sm[SCAN_B];
    int i = blockIdx.x * SCAN_B + threadIdx.x;
    int v = (i < n) ? g_cnt[i] : 0;
    sm[threadIdx.x] = v;
    __syncthreads();
    for (int off = 1; off < SCAN_B; off <<= 1) {
        int t = 0;
        if ((int)threadIdx.x >= off) t = sm[threadIdx.x - off];
        __syncthreads();
        if ((int)threadIdx.x >= off) sm[threadIdx.x] += t;
        __syncthreads();
    }
    if (i < n) g_rowptr[i] = g_blockoff[blockIdx.x] + sm[threadIdx.x] - v;
}

__global__ void fill_kernel(const void* __restrict__ ei, int E, int n) {
    int e = blockIdx.x * blockDim.x + threadIdx.x;
    if (e >= E) return;
    unsigned s = min((unsigned)edge_at(ei, e), (unsigned)(n - 1));
    unsigned d = min((unsigned)edge_at(ei, E + e), (unsigned)(n - 1));
    int pos = g_rowptr[d] + atomicAdd(&g_fill[d], 1);
    g_col[pos] = (int)s;
}

// ---------------------------------------------------------------------------
// Gather aggregation: msum[i] = mean over in-neighbors of h[col].
// One warp per node; lane owns 4 consecutive floats. No atomics.
// ---------------------------------------------------------------------------
template <int SRC>
__global__ void __launch_bounds__(256) agg_kernel(const float* __restrict__ x,
                                                  int n) {
    int tid = blockIdx.x * blockDim.x + threadIdx.x;
    int node = tid >> 5;
    if (node >= n) return;
    int lane = tid & 31;
    const float* h = (SRC == 0) ? x : g_h1;
    int beg = g_rowptr[node], end = g_rowptr[node + 1];
    float4 acc = make_float4(0.f, 0.f, 0.f, 0.f);
    for (int k = beg; k < end; ++k) {
        int c = g_col[k];
        const float4 v = *(const float4*)(h + (size_t)c * D + lane * 4);
        acc.x += v.x; acc.y += v.y; acc.z += v.z; acc.w += v.w;
    }
    float sc = 1.f / fmaxf((float)(end - beg), 1.f);
    acc.x *= sc; acc.y *= sc; acc.z *= sc; acc.w *= sc;
    *(float4*)(g_msum + (size_t)node * D + lane * 4) = acc;
}

// ---------------------------------------------------------------------------
// Fused SAGE layer: out = relu( msum @ Wl + bl + h @ Wr )   (msum is mean)
// 256 threads, 2 nodes/thread, 32 out cols/block (grid.y=4). FFMA2.
// ---------------------------------------------------------------------------
template <int SRC, int OUT>
__global__ void __launch_bounds__(256) sage_kernel(
    const float* __restrict__ x, const float* __restrict__ Wl,
    const float* __restrict__ bl, const float* __restrict__ Wr, int n) {
    __shared__ float sWl[D * 32];
    __shared__ float sWr[D * 32];
    __shared__ float sb[32];

    const int j0 = blockIdx.y * 32;
    for (int idx = threadIdx.x; idx < D * 32; idx += 256) {
        int k = idx >> 5, jj = idx & 31;
        sWl[idx] = Wl[k * D + j0 + jj];
        sWr[idx] = Wr[k * D + j0 + jj];
    }
    if (threadIdx.x < 32) sb[threadIdx.x] = bl[j0 + threadIdx.x];
    __syncthreads();

    const float* h = (SRC == 0) ? x : g_h1;
    float* out = (OUT == 1) ? g_h1 : g_h2;

    const int n0 = blockIdx.x * 512 + threadIdx.x;
    const int n1 = n0 + 256;
    const int c0 = min(n0, n - 1), c1 = min(n1, n - 1);
    const float4* m0p = (const float4*)(g_msum + (size_t)c0 * D);
    const float4* m1p = (const float4*)(g_msum + (size_t)c1 * D);
    const float4* h0p = (const float4*)(h + (size_t)c0 * D);
    const float4* h1p = (const float4*)(h + (size_t)c1 * D);

    unsigned long long acc0[16], acc1[16];
#pragma unroll
    for (int p = 0; p < 16; p++) {
        unsigned long long b = pack2(sb[2 * p], sb[2 * p + 1]);
        acc0[p] = b;
        acc1[p] = b;
    }

#pragma unroll 2
    for (int k4 = 0; k4 < 32; ++k4) {
        float4 m0 = m0p[k4], q0 = h0p[k4];
        float4 m1 = m1p[k4], q1 = h1p[k4];
        float a0s[4] = {m0.x, m0.y, m0.z, m0.w};
        float a1s[4] = {m1.x, m1.y, m1.z, m1.w};
        float r0s[4] = {q0.x, q0.y, q0.z, q0.w};
        float r1s[4] = {q1.x, q1.y, q1.z, q1.w};
#pragma unroll
        for (int kk = 0; kk < 4; ++kk) {
            const int kbase = (k4 * 4 + kk) * 32;
            unsigned long long pa0 = pack2(a0s[kk], a0s[kk]);
            unsigned long long pr0 = pack2(r0s[kk], r0s[kk]);
            unsigned long long pa1 = pack2(a1s[kk], a1s[kk]);
            unsigned long long pr1 = pack2(r1s[kk], r1s[kk]);
#pragma unroll
            for (int jj = 0; jj < 8; ++jj) {
                ulonglong2 wl = *(const ulonglong2*)&sWl[kbase + jj * 4];
                ulonglong2 wr = *(const ulonglong2*)&sWr[kbase + jj * 4];
                ffma2(acc0[jj * 2 + 0], pa0, wl.x);
                ffma2(acc0[jj * 2 + 0], pr0, wr.x);
                ffma2(acc0[jj * 2 + 1], pa0, wl.y);
                ffma2(acc0[jj * 2 + 1], pr0, wr.y);
                ffma2(acc1[jj * 2 + 0], pa1, wl.x);
                ffma2(acc1[jj * 2 + 0], pr1, wr.x);
                ffma2(acc1[jj * 2 + 1], pa1, wl.y);
                ffma2(acc1[jj * 2 + 1], pr1, wr.y);
            }
        }
    }

    if (n0 < n) {
        float4* o = (float4*)(out + (size_t)n0 * D + j0);
#pragma unroll
        for (int jj = 0; jj < 8; ++jj) {
            float2 a = unpack2(acc0[jj * 2 + 0]);
            float2 b = unpack2(acc0[jj * 2 + 1]);
            o[jj] = make_float4(fmaxf(a.x, 0.f), fmaxf(a.y, 0.f),
                                fmaxf(b.x, 0.f), fmaxf(b.y, 0.f));
        }
    }
    if (n1 < n) {
        float4* o = (float4*)(out + (size_t)n1 * D + j0);
#pragma unroll
        for (int jj = 0; jj < 8; ++jj) {
            float2 a = unpack2(acc1[jj * 2 + 0]);
            float2 b = unpack2(acc1[jj * 2 + 1]);
            o[jj] = make_float4(fmaxf(a.x, 0.f), fmaxf(a.y, 0.f),
                                fmaxf(b.x, 0.f), fmaxf(b.y, 0.f));
        }
    }
}

// ---------------------------------------------------------------------------
// Fused MLP head: out = relu( relu(g_h2 @ W0 + b0) @ W1 + b1 )
// ---------------------------------------------------------------------------
__global__ void __launch_bounds__(256) lin_kernel(
    const float* __restrict__ W0, const float* __restrict__ b0,
    const float* __restrict__ W1, const float* __restrict__ b1,
    float* __restrict__ out, int n) {
    __shared__ float sW0[D * 64];
    __shared__ float sW1[64 * 8];
    __shared__ float sb0[64];
    __shared__ float sb1[8];

    for (int idx = threadIdx.x; idx < D * 64; idx += 256) sW0[idx] = W0[idx];
    for (int idx = threadIdx.x; idx < 64 * 8; idx += 256) sW1[idx] = W1[idx];
    if (threadIdx.x < 64) sb0[threadIdx.x] = b0[threadIdx.x];
    if (threadIdx.x < 8) sb1[threadIdx.x] = b1[threadIdx.x];
    __syncthreads();

    const int n0 = blockIdx.x * 256 + threadIdx.x;
    const int c0 = min(n0, n - 1);
    const float4* hp = (const float4*)(g_h2 + (size_t)c0 * D);

    unsigned long long acc[32];
#pragma unroll
    for (int p = 0; p < 32; p++) acc[p] = pack2(sb0[2 * p], sb0[2 * p + 1]);

#pragma unroll 2
    for (int k4 = 0; k4 < 32; ++k4) {
        float4 hv = hp[k4];
        float r[4] = {hv.x, hv.y, hv.z, hv.w};
#pragma unroll
        for (int kk = 0; kk < 4; ++kk) {
            const int kbase = (k4 * 4 + kk) * 64;
            unsigned long long pr = pack2(r[kk], r[kk]);
#pragma unroll
            for (int jj = 0; jj < 16; ++jj) {
                ulonglong2 w = *(const ulonglong2*)&sW0[kbase + jj * 4];
                ffma2(acc[jj * 2 + 0], pr, w.x);
                ffma2(acc[jj * 2 + 1], pr, w.y);
            }
        }
    }

    float o[8];
#pragma unroll
    for (int j = 0; j < 8; j++) o[j] = sb1[j];
    const float4* W14 = (const float4*)sW1;
#pragma unroll
    for (int p = 0; p < 32; ++p) {
        float2 t2 = unpack2(acc[p]);
        float t0 = fmaxf(t2.x, 0.f);
        float t1 = fmaxf(t2.y, 0.f);
        {
            float4 wa = W14[(2 * p) * 2 + 0];
            float4 wb = W14[(2 * p) * 2 + 1];
            o[0] = fmaf(t0, wa.x, o[0]);
            o[1] = fmaf(t0, wa.y, o[1]);
            o[2] = fmaf(t0, wa.z, o[2]);
            o[3] = fmaf(t0, wa.w, o[3]);
            o[4] = fmaf(t0, wb.x, o[4]);
            o[5] = fmaf(t0, wb.y, o[5]);
            o[6] = fmaf(t0, wb.z, o[6]);
            o[7] = fmaf(t0, wb.w, o[7]);
        }
        {
            float4 wa = W14[(2 * p + 1) * 2 + 0];
            float4 wb = W14[(2 * p + 1) * 2 + 1];
            o[0] = fmaf(t1, wa.x, o[0]);
            o[1] = fmaf(t1, wa.y, o[1]);
            o[2] = fmaf(t1, wa.z, o[2]);
            o[3] = fmaf(t1, wa.w, o[3]);
            o[4] = fmaf(t1, wb.x, o[4]);
            o[5] = fmaf(t1, wb.y, o[5]);
            o[6] = fmaf(t1, wb.z, o[6]);
            o[7] = fmaf(t1, wb.w, o[7]);
        }
    }

    if (n0 < n) {
        float4* op = (float4*)(out + (size_t)n0 * 8);
        op[0] = make_float4(fmaxf(o[0], 0.f), fmaxf(o[1], 0.f),
                            fmaxf(o[2], 0.f), fmaxf(o[3], 0.f));
        op[1] = make_float4(fmaxf(o[4], 0.f), fmaxf(o[5], 0.f),
                            fmaxf(o[6], 0.f), fmaxf(o[7], 0.f));
    }
}

// ---------------------------------------------------------------------------
// Launcher (no allocation, graph-capturable)
// ---------------------------------------------------------------------------
extern "C" void kernel_launch(void* const* d_in, const int* in_sizes, int n_in,
                              void* d_out, int out_size) {
    const float* x    = (const float*)d_in[0];
    const void*  ei   = d_in[1];
    const float* s0Wl = (const float*)d_in[2];
    const float* s0bl = (const float*)d_in[3];
    const float* s0Wr = (const float*)d_in[4];
    const float* s1Wl = (const float*)d_in[5];
    const float* s1bl = (const float*)d_in[6];
    const float* s1Wr = (const float*)d_in[7];
    const float* l0W  = (const float*)d_in[8];
    const float* l0b  = (const float*)d_in[9];
    const float* l1W  = (const float*)d_in[10];
    const float* l1b  = (const float*)d_in[11];
    float* out = (float*)d_out;

    const int N = in_sizes[0] / D;
    const int E = in_sizes[1] / 2;
    const int NB = (N + SCAN_B - 1) / SCAN_B;

    detect_kernel<<<1, 256>>>((const unsigned int*)ei, 2048);

    // CSR build (once per launch; shared by both layers)
    zero_cnt_kernel<<<(N + 255) / 256, 256>>>(N);
    hist_kernel<<<(E + 255) / 256, 256>>>(ei, E, N);
    scan1_kernel<<<NB, SCAN_B>>>(N);
    scan2_kernel<<<1, 32>>>(NB, N, E);
    scan3_kernel<<<NB, SCAN_B>>>(N);
    fill_kernel<<<(E + 255) / 256, 256>>>(ei, E, N);

    const int agg_blocks = (int)(((long long)N * 32 + 255) / 256);
    dim3 sgrid((N + 511) / 512, 4);

    // layer 0
    agg_kernel<0><<<agg_blocks, 256>>>(x, N);
    sage_kernel<0, 1><<<sgrid, 256>>>(x, s0Wl, s0bl, s0Wr, N);

    // layer 1
    agg_kernel<1><<<agg_blocks, 256>>>(x, N);
    sage_kernel<1, 2><<<sgrid, 256>>>(x, s1Wl, s1bl, s1Wr, N);

    // MLP head
    lin_kernel<<<(N + 255) / 256, 256>>>(l0W, l0b, l1W, l1b, out, N);
}